// round 1
// baseline (speedup 1.0000x reference)
#include <cuda_runtime.h>

#define EMB   1024
#define NB    4
#define SEQ   4096
#define NROWS (NB*SEQ)   // 16384

#define BM  128
#define BN  128
#define BK  32
#define SLD 36   // smem row stride in floats: 144B rows (16B aligned), +4 pad kills bank conflicts

// Scratch (device globals: allocation-free per harness rules)
__device__ __align__(16) float g_q[(size_t)NB*SEQ*EMB];
__device__ __align__(16) float g_k[(size_t)NB*SEQ*EMB];
__device__ __align__(16) float g_v[(size_t)NB*SEQ*EMB];
__device__ __align__(16) float g_s[(size_t)NB*SEQ*SEQ];

__device__ __forceinline__ unsigned f2tf(float x){
    unsigned r; asm("cvt.rna.tf32.f32 %0, %1;" : "=r"(r) : "f"(x)); return r;
}

// C[M,N] = A[M,K](row-major) * B' + optional bias.
// BT_NK=true : B given as Bt[N,K] row-major (i.e., C = A * B^T)   -> QKV proj, Q*K^T
// BT_NK=false: B given as B[K,N] row-major  (C = A * B)           -> P*V
template<bool BT_NK, bool HAS_BIAS>
__global__ void __launch_bounds__(256,2) gemm_k(
    const float* __restrict__ A, int lda, long long sA,
    const float* __restrict__ B, int ldb, long long sB,
    const float* __restrict__ bias,
    float* __restrict__ C, int ldc, long long sC,
    int K)
{
    __shared__ float As[BM][SLD];
    __shared__ float Bs[BN][SLD];

    const int z = blockIdx.z;
    A += (size_t)z * sA;
    B += (size_t)z * sB;
    C += (size_t)z * sC;

    const int m0 = blockIdx.y * BM;
    const int n0 = blockIdx.x * BN;
    const int tid  = threadIdx.x;
    const int lane = tid & 31;
    const int wid  = tid >> 5;
    const int grp  = lane >> 2;   // 0..7
    const int qd   = lane & 3;    // 0..3
    const int wm0  = (wid >> 1) * 32;  // warp m-offset in tile
    const int wn0  = (wid & 1) * 64;   // warp n-offset in tile

    // global-load indexing
    const int lr  = tid >> 3;        // 0..31
    const int lc4 = (tid & 7) * 4;   // 0,4,...,28
    const int bk0 = tid >> 5;        // 0..7   (NN B loads)
    const int bn4 = (tid & 31) * 4;  // 0..124
    const int swz = tid & 31;        // == (bn4+i)>>2 for i in 0..3

    float c[2][8][4];
    #pragma unroll
    for (int mi = 0; mi < 2; mi++)
        #pragma unroll
        for (int ni = 0; ni < 8; ni++)
            #pragma unroll
            for (int j = 0; j < 4; j++) c[mi][ni][j] = 0.f;

    float4 ra[4], rb[4];
    const int KT = K / BK;

    auto LDG = [&](int kt){
        const float* Ap = A + (size_t)(m0 + lr) * lda + kt*BK + lc4;
        #pragma unroll
        for (int p = 0; p < 4; p++) ra[p] = *(const float4*)(Ap + (size_t)(p*32) * lda);
        if (BT_NK) {
            const float* Bp = B + (size_t)(n0 + lr) * ldb + kt*BK + lc4;
            #pragma unroll
            for (int p = 0; p < 4; p++) rb[p] = *(const float4*)(Bp + (size_t)(p*32) * ldb);
        } else {
            const float* Bp = B + (size_t)(kt*BK + bk0) * ldb + n0 + bn4;
            #pragma unroll
            for (int p = 0; p < 4; p++) rb[p] = *(const float4*)(Bp + (size_t)(p*8) * ldb);
        }
    };

    LDG(0);
    for (int kt = 0; kt < KT; kt++){
        // stage into smem
        #pragma unroll
        for (int p = 0; p < 4; p++)
            *(float4*)&As[lr + 32*p][lc4] = ra[p];
        if (BT_NK){
            #pragma unroll
            for (int p = 0; p < 4; p++)
                *(float4*)&Bs[lr + 32*p][lc4] = rb[p];
        } else {
            // transpose V tile into K-major smem, XOR-swizzled for conflict-free banks
            #pragma unroll
            for (int p = 0; p < 4; p++){
                const int kk = bk0 + 8*p;
                Bs[bn4+0][kk ^ swz] = rb[p].x;
                Bs[bn4+1][kk ^ swz] = rb[p].y;
                Bs[bn4+2][kk ^ swz] = rb[p].z;
                Bs[bn4+3][kk ^ swz] = rb[p].w;
            }
        }
        __syncthreads();
        if (kt + 1 < KT) LDG(kt + 1);   // prefetch next tile while computing this one

        #pragma unroll
        for (int ks = 0; ks < 4; ks++){
            const int kk = ks * 8;
            unsigned af[2][4];
            #pragma unroll
            for (int mi = 0; mi < 2; mi++){
                const int r = wm0 + mi*16 + grp;
                af[mi][0] = f2tf(As[r    ][kk + qd    ]);
                af[mi][1] = f2tf(As[r + 8][kk + qd    ]);
                af[mi][2] = f2tf(As[r    ][kk + qd + 4]);
                af[mi][3] = f2tf(As[r + 8][kk + qd + 4]);
            }
            #pragma unroll
            for (int ni = 0; ni < 8; ni++){
                const int col = wn0 + ni*8 + grp;
                unsigned b0, b1;
                if (BT_NK){
                    b0 = f2tf(Bs[col][kk + qd    ]);
                    b1 = f2tf(Bs[col][kk + qd + 4]);
                } else {
                    const int s2 = col >> 2;
                    b0 = f2tf(Bs[col][(kk + qd    ) ^ s2]);
                    b1 = f2tf(Bs[col][(kk + qd + 4) ^ s2]);
                }
                #pragma unroll
                for (int mi = 0; mi < 2; mi++){
                    asm volatile(
                        "mma.sync.aligned.m16n8k8.row.col.f32.tf32.tf32.f32 "
                        "{%0,%1,%2,%3},{%4,%5,%6,%7},{%8,%9},{%0,%1,%2,%3};"
                        : "+f"(c[mi][ni][0]), "+f"(c[mi][ni][1]),
                          "+f"(c[mi][ni][2]), "+f"(c[mi][ni][3])
                        : "r"(af[mi][0]), "r"(af[mi][1]), "r"(af[mi][2]), "r"(af[mi][3]),
                          "r"(b0), "r"(b1));
                }
            }
        }
        __syncthreads();
    }

    // epilogue: c0->(g,2q) c1->(g,2q+1) c2->(g+8,2q) c3->(g+8,2q+1)
    #pragma unroll
    for (int mi = 0; mi < 2; mi++){
        #pragma unroll
        for (int ni = 0; ni < 8; ni++){
            const int r  = m0 + wm0 + mi*16 + grp;
            const int cc = n0 + wn0 + ni*8 + qd*2;
            float2 v0 = make_float2(c[mi][ni][0], c[mi][ni][1]);
            float2 v1 = make_float2(c[mi][ni][2], c[mi][ni][3]);
            if (HAS_BIAS){
                float2 bb = *(const float2*)&bias[cc];
                v0.x += bb.x; v0.y += bb.y;
                v1.x += bb.x; v1.y += bb.y;
            }
            *(float2*)&C[(size_t)r     * ldc + cc] = v0;
            *(float2*)&C[(size_t)(r+8) * ldc + cc] = v1;
        }
    }
}

// Row softmax over SEQ=4096 fp32, scale folded in. One 256-thread CTA per row.
__global__ void __launch_bounds__(256) softmax_k(float* __restrict__ S)
{
    __shared__ float red[8];
    float* p = S + (size_t)blockIdx.x * SEQ;
    const int tid = threadIdx.x;
    const int lane = tid & 31, wid = tid >> 5;
    const float scale = 0.03125f;   // 1/sqrt(1024)

    float4 v[4];
    float mx = -1e30f;
    #pragma unroll
    for (int l = 0; l < 4; l++){
        v[l] = *(const float4*)(p + (size_t)(l*256 + tid) * 4);
        v[l].x *= scale; v[l].y *= scale; v[l].z *= scale; v[l].w *= scale;
        mx = fmaxf(mx, fmaxf(fmaxf(v[l].x, v[l].y), fmaxf(v[l].z, v[l].w)));
    }
    #pragma unroll
    for (int o = 16; o; o >>= 1) mx = fmaxf(mx, __shfl_xor_sync(0xffffffffu, mx, o));
    if (lane == 0) red[wid] = mx;
    __syncthreads();
    mx = red[0];
    #pragma unroll
    for (int w = 1; w < 8; w++) mx = fmaxf(mx, red[w]);
    __syncthreads();

    float sum = 0.f;
    #pragma unroll
    for (int l = 0; l < 4; l++){
        v[l].x = __expf(v[l].x - mx);
        v[l].y = __expf(v[l].y - mx);
        v[l].z = __expf(v[l].z - mx);
        v[l].w = __expf(v[l].w - mx);
        sum += v[l].x + v[l].y + v[l].z + v[l].w;
    }
    #pragma unroll
    for (int o = 16; o; o >>= 1) sum += __shfl_xor_sync(0xffffffffu, sum, o);
    if (lane == 0) red[wid] = sum;
    __syncthreads();
    sum = red[0];
    #pragma unroll
    for (int w = 1; w < 8; w++) sum += red[w];
    const float inv = 1.0f / sum;

    #pragma unroll
    for (int l = 0; l < 4; l++){
        v[l].x *= inv; v[l].y *= inv; v[l].z *= inv; v[l].w *= inv;
        *(float4*)(p + (size_t)(l*256 + tid) * 4) = v[l];
    }
}

extern "C" void kernel_launch(void* const* d_in, const int* in_sizes, int n_in,
                              void* d_out, int out_size)
{
    (void)in_sizes; (void)n_in; (void)out_size;
    const float* X  = (const float*)d_in[0];
    const float* Wq = (const float*)d_in[1];
    const float* bq = (const float*)d_in[2];
    const float* Wk = (const float*)d_in[3];
    const float* bk = (const float*)d_in[4];
    const float* Wv = (const float*)d_in[5];
    const float* bv = (const float*)d_in[6];
    float* out = (float*)d_out;

    float *q, *k, *v, *s;
    cudaGetSymbolAddress((void**)&q, g_q);
    cudaGetSymbolAddress((void**)&k, g_k);
    cudaGetSymbolAddress((void**)&v, g_v);
    cudaGetSymbolAddress((void**)&s, g_s);

    dim3 blk(256, 1, 1);

    // QKV projections: C[16384,1024] = X @ W^T + b
    dim3 gqkv(EMB/BN, NROWS/BM, 1);
    gemm_k<true,  true ><<<gqkv, blk>>>(X, EMB, 0, Wq, EMB, 0, bq, q, EMB, 0, EMB);
    gemm_k<true,  true ><<<gqkv, blk>>>(X, EMB, 0, Wk, EMB, 0, bk, k, EMB, 0, EMB);
    gemm_k<true,  true ><<<gqkv, blk>>>(X, EMB, 0, Wv, EMB, 0, bv, v, EMB, 0, EMB);

    // scores[b] = Q[b] @ K[b]^T   (scale applied in softmax)
    dim3 gsc(SEQ/BN, SEQ/BM, NB);
    gemm_k<true,  false><<<gsc, blk>>>(q, EMB, (long long)SEQ*EMB,
                                       k, EMB, (long long)SEQ*EMB,
                                       nullptr,
                                       s, SEQ, (long long)SEQ*SEQ, EMB);

    // softmax over rows (B*S rows of length S)
    softmax_k<<<NROWS, 256>>>(s);

    // out[b] = P[b] @ V[b]
    dim3 gav(EMB/BN, SEQ/BM, NB);
    gemm_k<false, false><<<gav, blk>>>(s,  SEQ, (long long)SEQ*SEQ,
                                       v,  EMB, (long long)SEQ*EMB,
                                       nullptr,
                                       out, EMB, (long long)SEQ*EMB, SEQ);
}

// round 2
// speedup vs baseline: 1.1630x; 1.1630x over previous
#include <cuda_runtime.h>

#define EMB   1024
#define NB    4
#define SEQ   4096
#define NROWS (NB*SEQ)   // 16384

#define BM  128
#define BN  128
#define BK  32
#define SLD 36   // smem row stride (floats/words): stride%32==4 -> bank = 4*grp+qd, bijective, conflict-free

// Scratch (device globals: allocation-free per harness rules)
__device__ __align__(16) float g_q[(size_t)NB*SEQ*EMB];
__device__ __align__(16) float g_k[(size_t)NB*SEQ*EMB];
__device__ __align__(16) float g_v[(size_t)NB*SEQ*EMB];
__device__ __align__(16) float g_s[(size_t)NB*SEQ*SEQ];

__device__ __forceinline__ unsigned f2tf(float x){
    unsigned r; asm("cvt.rna.tf32.f32 %0, %1;" : "=r"(r) : "f"(x)); return r;
}

// C[M,N] = A[M,K](row-major) * B' + optional bias.   tf32 HMMA, smem holds pre-converted tf32.
// BT_NK=true : B given as Bt[N,K] row-major (C = A * B^T)  -> QKV proj, Q*K^T
// BT_NK=false: B given as B[K,N] row-major  (C = A * B)    -> P*V
template<bool BT_NK, bool HAS_BIAS>
__global__ void __launch_bounds__(256,2) gemm_k(
    const float* __restrict__ A, int lda, long long sA,
    const float* __restrict__ B, int ldb, long long sB,
    const float* __restrict__ bias,
    float* __restrict__ C, int ldc, long long sC,
    int K)
{
    // double-buffered: As[2][BM][SLD], Bs[2][BN][SLD] of tf32 bit patterns
    extern __shared__ unsigned sm[];
    unsigned* Asm = sm;
    unsigned* Bsm = sm + 2*BM*SLD;

    const int z = blockIdx.z;
    A += (size_t)z * sA;
    B += (size_t)z * sB;
    C += (size_t)z * sC;

    const int m0 = blockIdx.y * BM;
    const int n0 = blockIdx.x * BN;
    const int tid  = threadIdx.x;
    const int lane = tid & 31;
    const int wid  = tid >> 5;
    const int grp  = lane >> 2;   // 0..7
    const int qd   = lane & 3;    // 0..3
    const int wm0  = (wid >> 1) * 32;  // warp m-offset in tile
    const int wn0  = (wid & 1) * 64;   // warp n-offset in tile

    // global-load indexing
    const int lr  = tid >> 3;        // 0..31
    const int lc4 = (tid & 7) * 4;   // 0,4,...,28
    const int bk0 = tid >> 5;        // 0..7   (NN B loads)
    const int bn4 = (tid & 31) * 4;  // 0..124
    const int swz = tid & 31;        // == (bn4+i)>>2 for i in 0..3

    float c[2][8][4];
    #pragma unroll
    for (int mi = 0; mi < 2; mi++)
        #pragma unroll
        for (int ni = 0; ni < 8; ni++)
            #pragma unroll
            for (int j = 0; j < 4; j++) c[mi][ni][j] = 0.f;

    float4 ra[4], rb[4];
    const int KT = K / BK;

    auto LDG = [&](int kt){
        const float* Ap = A + (size_t)(m0 + lr) * lda + kt*BK + lc4;
        #pragma unroll
        for (int p = 0; p < 4; p++) ra[p] = *(const float4*)(Ap + (size_t)(p*32) * lda);
        if (BT_NK) {
            const float* Bp = B + (size_t)(n0 + lr) * ldb + kt*BK + lc4;
            #pragma unroll
            for (int p = 0; p < 4; p++) rb[p] = *(const float4*)(Bp + (size_t)(p*32) * ldb);
        } else {
            const float* Bp = B + (size_t)(kt*BK + bk0) * ldb + n0 + bn4;
            #pragma unroll
            for (int p = 0; p < 4; p++) rb[p] = *(const float4*)(Bp + (size_t)(p*8) * ldb);
        }
    };

    // convert to tf32 and stage into smem stage s
    auto STS = [&](int s){
        unsigned* Ap = Asm + s * BM * SLD;
        #pragma unroll
        for (int p = 0; p < 4; p++){
            uint4 t;
            t.x = f2tf(ra[p].x); t.y = f2tf(ra[p].y);
            t.z = f2tf(ra[p].z); t.w = f2tf(ra[p].w);
            *(uint4*)&Ap[(lr + 32*p)*SLD + lc4] = t;
        }
        unsigned* Bp = Bsm + s * BN * SLD;
        if (BT_NK){
            #pragma unroll
            for (int p = 0; p < 4; p++){
                uint4 t;
                t.x = f2tf(rb[p].x); t.y = f2tf(rb[p].y);
                t.z = f2tf(rb[p].z); t.w = f2tf(rb[p].w);
                *(uint4*)&Bp[(lr + 32*p)*SLD + lc4] = t;
            }
        } else {
            // transpose V tile into K-major smem, XOR-swizzled for conflict-free banks
            #pragma unroll
            for (int p = 0; p < 4; p++){
                const int kk = bk0 + 8*p;
                Bp[(bn4+0)*SLD + (kk ^ swz)] = f2tf(rb[p].x);
                Bp[(bn4+1)*SLD + (kk ^ swz)] = f2tf(rb[p].y);
                Bp[(bn4+2)*SLD + (kk ^ swz)] = f2tf(rb[p].z);
                Bp[(bn4+3)*SLD + (kk ^ swz)] = f2tf(rb[p].w);
            }
        }
    };

    LDG(0);
    STS(0);
    __syncthreads();

    for (int kt = 0; kt < KT; kt++){
        if (kt + 1 < KT) LDG(kt + 1);

        const unsigned* Ac = Asm + (kt & 1) * BM * SLD;
        const unsigned* Bc = Bsm + (kt & 1) * BN * SLD;

        #pragma unroll
        for (int ks = 0; ks < 4; ks++){
            const int kk = ks * 8;
            unsigned af[2][4];
            #pragma unroll
            for (int mi = 0; mi < 2; mi++){
                const int r = wm0 + mi*16 + grp;
                af[mi][0] = Ac[(r    )*SLD + kk + qd    ];
                af[mi][1] = Ac[(r + 8)*SLD + kk + qd    ];
                af[mi][2] = Ac[(r    )*SLD + kk + qd + 4];
                af[mi][3] = Ac[(r + 8)*SLD + kk + qd + 4];
            }
            #pragma unroll
            for (int ni = 0; ni < 8; ni++){
                const int col = wn0 + ni*8 + grp;
                unsigned b0, b1;
                if (BT_NK){
                    b0 = Bc[col*SLD + kk + qd    ];
                    b1 = Bc[col*SLD + kk + qd + 4];
                } else {
                    const int s2 = col >> 2;
                    b0 = Bc[col*SLD + ((kk + qd    ) ^ s2)];
                    b1 = Bc[col*SLD + ((kk + qd + 4) ^ s2)];
                }
                #pragma unroll
                for (int mi = 0; mi < 2; mi++){
                    asm volatile(
                        "mma.sync.aligned.m16n8k8.row.col.f32.tf32.tf32.f32 "
                        "{%0,%1,%2,%3},{%4,%5,%6,%7},{%8,%9},{%0,%1,%2,%3};"
                        : "+f"(c[mi][ni][0]), "+f"(c[mi][ni][1]),
                          "+f"(c[mi][ni][2]), "+f"(c[mi][ni][3])
                        : "r"(af[mi][0]), "r"(af[mi][1]), "r"(af[mi][2]), "r"(af[mi][3]),
                          "r"(b0), "r"(b1));
                }
            }
        }

        if (kt + 1 < KT){
            STS((kt + 1) & 1);   // writes the stage NOT being computed this iteration
            __syncthreads();
        }
    }

    // epilogue: c0->(g,2q) c1->(g,2q+1) c2->(g+8,2q) c3->(g+8,2q+1)
    #pragma unroll
    for (int mi = 0; mi < 2; mi++){
        #pragma unroll
        for (int ni = 0; ni < 8; ni++){
            const int r  = m0 + wm0 + mi*16 + grp;
            const int cc = n0 + wn0 + ni*8 + qd*2;
            float2 v0 = make_float2(c[mi][ni][0], c[mi][ni][1]);
            float2 v1 = make_float2(c[mi][ni][2], c[mi][ni][3]);
            if (HAS_BIAS){
                float2 bb = *(const float2*)&bias[cc];
                v0.x += bb.x; v0.y += bb.y;
                v1.x += bb.x; v1.y += bb.y;
            }
            *(float2*)&C[(size_t)r     * ldc + cc] = v0;
            *(float2*)&C[(size_t)(r+8) * ldc + cc] = v1;
        }
    }
}

// Row softmax over SEQ=4096 fp32, scale folded in. One 256-thread CTA per row.
__global__ void __launch_bounds__(256) softmax_k(float* __restrict__ S)
{
    __shared__ float red[8];
    float* p = S + (size_t)blockIdx.x * SEQ;
    const int tid = threadIdx.x;
    const int lane = tid & 31, wid = tid >> 5;
    const float scale = 0.03125f;   // 1/sqrt(1024)

    float4 v[4];
    float mx = -1e30f;
    #pragma unroll
    for (int l = 0; l < 4; l++){
        v[l] = *(const float4*)(p + (size_t)(l*256 + tid) * 4);
        v[l].x *= scale; v[l].y *= scale; v[l].z *= scale; v[l].w *= scale;
        mx = fmaxf(mx, fmaxf(fmaxf(v[l].x, v[l].y), fmaxf(v[l].z, v[l].w)));
    }
    #pragma unroll
    for (int o = 16; o; o >>= 1) mx = fmaxf(mx, __shfl_xor_sync(0xffffffffu, mx, o));
    if (lane == 0) red[wid] = mx;
    __syncthreads();
    mx = red[0];
    #pragma unroll
    for (int w = 1; w < 8; w++) mx = fmaxf(mx, red[w]);
    __syncthreads();

    float sum = 0.f;
    #pragma unroll
    for (int l = 0; l < 4; l++){
        v[l].x = __expf(v[l].x - mx);
        v[l].y = __expf(v[l].y - mx);
        v[l].z = __expf(v[l].z - mx);
        v[l].w = __expf(v[l].w - mx);
        sum += v[l].x + v[l].y + v[l].z + v[l].w;
    }
    #pragma unroll
    for (int o = 16; o; o >>= 1) sum += __shfl_xor_sync(0xffffffffu, sum, o);
    if (lane == 0) red[wid] = sum;
    __syncthreads();
    sum = red[0];
    #pragma unroll
    for (int w = 1; w < 8; w++) sum += red[w];
    const float inv = 1.0f / sum;

    #pragma unroll
    for (int l = 0; l < 4; l++){
        v[l].x *= inv; v[l].y *= inv; v[l].z *= inv; v[l].w *= inv;
        *(float4*)(p + (size_t)(l*256 + tid) * 4) = v[l];
    }
}

extern "C" void kernel_launch(void* const* d_in, const int* in_sizes, int n_in,
                              void* d_out, int out_size)
{
    (void)in_sizes; (void)n_in; (void)out_size;
    const float* X  = (const float*)d_in[0];
    const float* Wq = (const float*)d_in[1];
    const float* bq = (const float*)d_in[2];
    const float* Wk = (const float*)d_in[3];
    const float* bk = (const float*)d_in[4];
    const float* Wv = (const float*)d_in[5];
    const float* bv = (const float*)d_in[6];
    float* out = (float*)d_out;

    float *q, *k, *v, *s;
    cudaGetSymbolAddress((void**)&q, g_q);
    cudaGetSymbolAddress((void**)&k, g_k);
    cudaGetSymbolAddress((void**)&v, g_v);
    cudaGetSymbolAddress((void**)&s, g_s);

    const size_t smem = (size_t)2 * (BM + BN) * SLD * sizeof(unsigned);  // 73728 B
    cudaFuncSetAttribute(gemm_k<true,  true >, cudaFuncAttributeMaxDynamicSharedMemorySize, (int)smem);
    cudaFuncSetAttribute(gemm_k<true,  false>, cudaFuncAttributeMaxDynamicSharedMemorySize, (int)smem);
    cudaFuncSetAttribute(gemm_k<false, false>, cudaFuncAttributeMaxDynamicSharedMemorySize, (int)smem);

    dim3 blk(256, 1, 1);

    // QKV projections: C[16384,1024] = X @ W^T + b
    dim3 gqkv(EMB/BN, NROWS/BM, 1);
    gemm_k<true,  true ><<<gqkv, blk, smem>>>(X, EMB, 0, Wq, EMB, 0, bq, q, EMB, 0, EMB);
    gemm_k<true,  true ><<<gqkv, blk, smem>>>(X, EMB, 0, Wk, EMB, 0, bk, k, EMB, 0, EMB);
    gemm_k<true,  true ><<<gqkv, blk, smem>>>(X, EMB, 0, Wv, EMB, 0, bv, v, EMB, 0, EMB);

    // scores[b] = Q[b] @ K[b]^T   (scale applied in softmax)
    dim3 gsc(SEQ/BN, SEQ/BM, NB);
    gemm_k<true,  false><<<gsc, blk, smem>>>(q, EMB, (long long)SEQ*EMB,
                                             k, EMB, (long long)SEQ*EMB,
                                             nullptr,
                                             s, SEQ, (long long)SEQ*SEQ, EMB);

    // softmax over rows (B*S rows of length S)
    softmax_k<<<NROWS, 256>>>(s);

    // out[b] = P[b] @ V[b]
    dim3 gav(EMB/BN, SEQ/BM, NB);
    gemm_k<false, false><<<gav, blk, smem>>>(s,  SEQ, (long long)SEQ*SEQ,
                                             v,  EMB, (long long)SEQ*EMB,
                                             nullptr,
                                             out, EMB, (long long)SEQ*EMB, SEQ);
}

// round 4
// speedup vs baseline: 2.0409x; 1.7549x over previous
#include <cuda_runtime.h>
#include <cuda_fp16.h>
#include <cstdint>

#define EMB   1024
#define NB    4
#define SEQ   4096
#define NROWS (NB*SEQ)   // 16384

#define BM   128
#define BN   128
#define BK   32          // K elements per smem tile (2 x k16 mma steps)
#define SLDW 20          // smem row stride in 32-bit words (=40 halves): bank=20r+q, conflict-free

// fp16 scratch (device globals: allocation-free per harness rules)
__device__ __align__(1024) __half g_qh [(size_t)NB*SEQ*EMB];
__device__ __align__(1024) __half g_kh [(size_t)NB*SEQ*EMB];
__device__ __align__(1024) __half g_vth[(size_t)NB*SEQ*EMB];   // Vt[E, B*S]
__device__ __align__(1024) __half g_sh [(size_t)NB*SEQ*SEQ];   // scores / probs

__device__ __forceinline__ unsigned packh2(float x, float y){
    __half2 h = __floats2half2_rn(x, y);
    return *reinterpret_cast<unsigned*>(&h);
}
__device__ __forceinline__ float2 h2f2(unsigned u){
    __half2 h = *reinterpret_cast<__half2*>(&u);
    return __half22float2(h);
}

__device__ __forceinline__ void mma16816(float c[4], const unsigned a[4],
                                         unsigned b0, unsigned b1){
    asm volatile(
        "mma.sync.aligned.m16n8k16.row.col.f32.f16.f16.f32 "
        "{%0,%1,%2,%3},{%4,%5,%6,%7},{%8,%9},{%0,%1,%2,%3};"
        : "+f"(c[0]), "+f"(c[1]), "+f"(c[2]), "+f"(c[3])
        : "r"(a[0]), "r"(a[1]), "r"(a[2]), "r"(a[3]), "r"(b0), "r"(b1));
}

// C[M,N] = A[M,K] * B[N,K]^T (+bias). K-major A and B. fp16 tensor cores, fp32 accum.
// AH/BH: input dtype is half (else float). OH: output half (else float).
// bias_mode: 0 none, 1 col (bias[n]), 2 row (bias[m]).
// bko: per-batch column offset into B's K dimension (for PV slicing Vt).
template<bool AH, bool BH, bool OH>
__global__ void __launch_bounds__(256,2) gemm_h(
    const void* __restrict__ A_, int lda, long long sA,
    const void* __restrict__ B_, int ldb, long long sB,
    const float* __restrict__ bias, int bias_mode,
    void* __restrict__ C_, int ldc, long long sC,
    int K, int bko)
{
    __shared__ unsigned As[2][BM][SLDW];   // half2-packed, 20 words = 40 halves (32 used)
    __shared__ unsigned Bs[2][BN][SLDW];

    const int z = blockIdx.z;
    const int m0 = blockIdx.y * BM;
    const int n0 = blockIdx.x * BN;
    const int tid  = threadIdx.x;
    const int lane = tid & 31;
    const int wid  = tid >> 5;
    const int grp  = lane >> 2;   // 0..7
    const int qd   = lane & 3;    // 0..3
    const int wm0  = (wid >> 1) * 32;
    const int wn0  = (wid & 1) * 64;

    const int lr = tid >> 3;         // 0..31 (row group)
    const int cg = tid & 7;          // 0..7  (column group of 4 elements)

    float c[2][8][4];
    #pragma unroll
    for (int mi = 0; mi < 2; mi++)
        #pragma unroll
        for (int ni = 0; ni < 8; ni++)
            #pragma unroll
            for (int j = 0; j < 4; j++) c[mi][ni][j] = 0.f;

    float4 raf[4], rbf[4];
    uint2  rah[4], rbh[4];
    const int KT = K / BK;
    const int kbase = z * bko;

    auto LDG = [&](int kt){
        if (AH){
            const __half* A = (const __half*)A_ + (size_t)z*sA;
            const __half* Ap = A + (size_t)(m0 + lr)*lda + kt*BK + cg*4;
            #pragma unroll
            for (int p = 0; p < 4; p++) rah[p] = *(const uint2*)(Ap + (size_t)(p*32)*lda);
        } else {
            const float* A = (const float*)A_ + (size_t)z*sA;
            const float* Ap = A + (size_t)(m0 + lr)*lda + kt*BK + cg*4;
            #pragma unroll
            for (int p = 0; p < 4; p++) raf[p] = *(const float4*)(Ap + (size_t)(p*32)*lda);
        }
        if (BH){
            const __half* B = (const __half*)B_ + (size_t)z*sB;
            const __half* Bp = B + (size_t)(n0 + lr)*ldb + kbase + kt*BK + cg*4;
            #pragma unroll
            for (int p = 0; p < 4; p++) rbh[p] = *(const uint2*)(Bp + (size_t)(p*32)*ldb);
        } else {
            const float* B = (const float*)B_ + (size_t)z*sB;
            const float* Bp = B + (size_t)(n0 + lr)*ldb + kbase + kt*BK + cg*4;
            #pragma unroll
            for (int p = 0; p < 4; p++) rbf[p] = *(const float4*)(Bp + (size_t)(p*32)*ldb);
        }
    };

    auto STS = [&](int s){
        #pragma unroll
        for (int p = 0; p < 4; p++){
            uint2 ta, tb;
            if (AH) ta = rah[p];
            else { ta.x = packh2(raf[p].x, raf[p].y); ta.y = packh2(raf[p].z, raf[p].w); }
            if (BH) tb = rbh[p];
            else { tb.x = packh2(rbf[p].x, rbf[p].y); tb.y = packh2(rbf[p].z, rbf[p].w); }
            *(uint2*)&As[s][lr + 32*p][cg*2] = ta;
            *(uint2*)&Bs[s][lr + 32*p][cg*2] = tb;
        }
    };

    LDG(0);
    STS(0);
    __syncthreads();

    for (int kt = 0; kt < KT; kt++){
        if (kt + 1 < KT) LDG(kt + 1);
        const int buf = kt & 1;

        #pragma unroll
        for (int ks = 0; ks < 2; ks++){       // two k16 steps per BK=32 tile
            const int kw = ks * 8;            // word offset: 8 words = 16 halves
            unsigned af[2][4];
            #pragma unroll
            for (int mi = 0; mi < 2; mi++){
                const int r = wm0 + mi*16 + grp;
                af[mi][0] = As[buf][r    ][kw + qd    ];
                af[mi][1] = As[buf][r + 8][kw + qd    ];
                af[mi][2] = As[buf][r    ][kw + qd + 4];
                af[mi][3] = As[buf][r + 8][kw + qd + 4];
            }
            #pragma unroll
            for (int ni = 0; ni < 8; ni++){
                const int col = wn0 + ni*8 + grp;
                const unsigned b0 = Bs[buf][col][kw + qd    ];
                const unsigned b1 = Bs[buf][col][kw + qd + 4];
                mma16816(c[0][ni], af[0], b0, b1);
                mma16816(c[1][ni], af[1], b0, b1);
            }
        }

        if (kt + 1 < KT){
            STS((kt + 1) & 1);
            __syncthreads();
        }
    }

    // epilogue: c0->(r,cc) c1->(r,cc+1) c2->(r+8,cc) c3->(r+8,cc+1)
    #pragma unroll
    for (int mi = 0; mi < 2; mi++){
        #pragma unroll
        for (int ni = 0; ni < 8; ni++){
            const int r  = m0 + wm0 + mi*16 + grp;
            const int cc = n0 + wn0 + ni*8 + qd*2;
            float v0 = c[mi][ni][0], v1 = c[mi][ni][1];
            float v2 = c[mi][ni][2], v3 = c[mi][ni][3];
            if (bias_mode == 1){
                const float b0 = bias[cc], b1 = bias[cc+1];
                v0 += b0; v1 += b1; v2 += b0; v3 += b1;
            } else if (bias_mode == 2){
                const float b0 = bias[r], b1 = bias[r+8];
                v0 += b0; v1 += b0; v2 += b1; v3 += b1;
            }
            if (OH){
                __half* C = (__half*)C_ + (size_t)z*sC;
                __half2 h0 = __floats2half2_rn(v0, v1);
                __half2 h1 = __floats2half2_rn(v2, v3);
                *(__half2*)&C[(size_t)r     * ldc + cc] = h0;
                *(__half2*)&C[(size_t)(r+8) * ldc + cc] = h1;
            } else {
                float* C = (float*)C_ + (size_t)z*sC;
                *(float2*)&C[(size_t)r     * ldc + cc] = make_float2(v0, v1);
                *(float2*)&C[(size_t)(r+8) * ldc + cc] = make_float2(v2, v3);
            }
        }
    }
}

// Row softmax over SEQ=4096 fp16 in/out, scale folded in, fp32 math.
__global__ void __launch_bounds__(256) softmax_h(__half* __restrict__ S)
{
    __shared__ float red[8];
    __half* p = S + (size_t)blockIdx.x * SEQ;
    const int tid = threadIdx.x;
    const int lane = tid & 31, wid = tid >> 5;
    const float scale = 0.03125f;   // 1/sqrt(1024)

    uint4 u[2];
    u[0] = ((const uint4*)p)[tid];
    u[1] = ((const uint4*)p)[tid + 256];

    float f[16];
    {
        const unsigned* w = (const unsigned*)u;
        #pragma unroll
        for (int i = 0; i < 8; i++){
            float2 t = h2f2(w[i]);
            f[2*i]   = t.x * scale;
            f[2*i+1] = t.y * scale;
        }
    }

    float mx = -1e30f;
    #pragma unroll
    for (int i = 0; i < 16; i++) mx = fmaxf(mx, f[i]);
    #pragma unroll
    for (int o = 16; o; o >>= 1) mx = fmaxf(mx, __shfl_xor_sync(0xffffffffu, mx, o));
    if (lane == 0) red[wid] = mx;
    __syncthreads();
    mx = red[0];
    #pragma unroll
    for (int w = 1; w < 8; w++) mx = fmaxf(mx, red[w]);
    __syncthreads();

    float sum = 0.f;
    #pragma unroll
    for (int i = 0; i < 16; i++){ f[i] = __expf(f[i] - mx); sum += f[i]; }
    #pragma unroll
    for (int o = 16; o; o >>= 1) sum += __shfl_xor_sync(0xffffffffu, sum, o);
    if (lane == 0) red[wid] = sum;
    __syncthreads();
    sum = red[0];
    #pragma unroll
    for (int w = 1; w < 8; w++) sum += red[w];
    const float inv = 1.0f / sum;

    {
        unsigned* w = (unsigned*)u;
        #pragma unroll
        for (int i = 0; i < 8; i++) w[i] = packh2(f[2*i]*inv, f[2*i+1]*inv);
    }
    ((uint4*)p)[tid]       = u[0];
    ((uint4*)p)[tid + 256] = u[1];
}

extern "C" void kernel_launch(void* const* d_in, const int* in_sizes, int n_in,
                              void* d_out, int out_size)
{
    (void)in_sizes; (void)n_in; (void)out_size;
    const float* X  = (const float*)d_in[0];
    const float* Wq = (const float*)d_in[1];
    const float* bq = (const float*)d_in[2];
    const float* Wk = (const float*)d_in[3];
    const float* bk = (const float*)d_in[4];
    const float* Wv = (const float*)d_in[5];
    const float* bv = (const float*)d_in[6];
    float* out = (float*)d_out;

    __half *qh, *kh, *vth, *sh;
    cudaGetSymbolAddress((void**)&qh,  g_qh);
    cudaGetSymbolAddress((void**)&kh,  g_kh);
    cudaGetSymbolAddress((void**)&vth, g_vth);
    cudaGetSymbolAddress((void**)&sh,  g_sh);

    dim3 blk(256, 1, 1);

    // 1) q = X @ Wq^T + bq   -> fp16 [16384, 1024]
    gemm_h<false,false,true><<<dim3(EMB/BN, NROWS/BM, 1), blk>>>(
        X, EMB, 0, Wq, EMB, 0, bq, 1, qh, EMB, 0, EMB, 0);
    // 2) k = X @ Wk^T + bk
    gemm_h<false,false,true><<<dim3(EMB/BN, NROWS/BM, 1), blk>>>(
        X, EMB, 0, Wk, EMB, 0, bk, 1, kh, EMB, 0, EMB, 0);
    // 3) Vt = Wv @ X^T + bv(row)  -> fp16 [1024, 16384]
    gemm_h<false,false,true><<<dim3(NROWS/BN, EMB/BM, 1), blk>>>(
        Wv, EMB, 0, X, EMB, 0, bv, 2, vth, NROWS, 0, EMB, 0);
    // 4) S[b] = q[b] @ k[b]^T  -> fp16 scores (scale folded into softmax)
    gemm_h<true,true,true><<<dim3(SEQ/BN, SEQ/BM, NB), blk>>>(
        qh, EMB, (long long)SEQ*EMB, kh, EMB, (long long)SEQ*EMB, nullptr, 0,
        sh, SEQ, (long long)SEQ*SEQ, EMB, 0);
    // 5) softmax rows (fp16 in/out, fp32 math)
    softmax_h<<<NROWS, 256>>>(sh);
    // 6) out[b] = P[b] @ Vt[:, b*S:(b+1)*S]^T  -> fp32
    gemm_h<true,true,false><<<dim3(EMB/BN, SEQ/BM, NB), blk>>>(
        sh, SEQ, (long long)SEQ*SEQ, vth, NROWS, 0, nullptr, 0,
        out, EMB, (long long)SEQ*EMB, SEQ, SEQ);
}

// round 5
// speedup vs baseline: 2.8009x; 1.3723x over previous
#include <cuda_runtime.h>
#include <cuda_fp16.h>
#include <cstdint>

#define EMB   1024
#define NB    4
#define SEQ   4096
#define NROWS (NB*SEQ)   // 16384

#define BM    128        // CTA M tile
#define BN    256        // CTA N tile
#define BKH   64         // K halves per stage (4 x k16)
#define SROWW 36         // smem row stride in words (=72 halves=144B); 36%32==4 -> conflict-free frags
#define NKS   4          // k16 steps per stage

// fp16 scratch (device globals: allocation-free per harness rules)
__device__ __align__(1024) __half g_xh [(size_t)NROWS*EMB];
__device__ __align__(1024) __half g_wqh[(size_t)EMB*EMB];
__device__ __align__(1024) __half g_wkh[(size_t)EMB*EMB];
__device__ __align__(1024) __half g_wvh[(size_t)EMB*EMB];
__device__ __align__(1024) __half g_qh [(size_t)NB*SEQ*EMB];
__device__ __align__(1024) __half g_kh [(size_t)NB*SEQ*EMB];
__device__ __align__(1024) __half g_vth[(size_t)NB*SEQ*EMB];   // Vt[E, B*S]
__device__ __align__(1024) __half g_sh [(size_t)NB*SEQ*SEQ];   // scores / probs

__device__ __forceinline__ unsigned packh2(float x, float y){
    __half2 h = __floats2half2_rn(x, y);
    return *reinterpret_cast<unsigned*>(&h);
}
__device__ __forceinline__ float2 h2f2(unsigned u){
    __half2 h = *reinterpret_cast<__half2*>(&u);
    return __half22float2(h);
}
__device__ __forceinline__ uint32_t smem_u32(const void* p){
    uint32_t a;
    asm("{ .reg .u64 t; cvta.to.shared.u64 t, %1; cvt.u32.u64 %0, t; }" : "=r"(a) : "l"(p));
    return a;
}
__device__ __forceinline__ void cp16(uint32_t s, const void* g){
    asm volatile("cp.async.ca.shared.global [%0], [%1], 16;" :: "r"(s), "l"(g));
}
#define CP_COMMIT() asm volatile("cp.async.commit_group;" ::: "memory")
#define CP_WAIT(N)  asm volatile("cp.async.wait_group %0;" :: "n"(N) : "memory")

__device__ __forceinline__ void mma16816(float c[4], const unsigned a[4],
                                         unsigned b0, unsigned b1){
    asm volatile(
        "mma.sync.aligned.m16n8k16.row.col.f32.f16.f16.f32 "
        "{%0,%1,%2,%3},{%4,%5,%6,%7},{%8,%9},{%0,%1,%2,%3};"
        : "+f"(c[0]), "+f"(c[1]), "+f"(c[2]), "+f"(c[3])
        : "r"(a[0]), "r"(a[1]), "r"(a[2]), "r"(a[3]), "r"(b0), "r"(b1));
}

// C[M,N] = A[M,K] * B[N,K]^T (+bias). All-fp16 inputs, K-major, fp32 accum.
// OH: output half (else float). bias_mode: 0 none, 1 col bias[n], 2 row bias[m].
// bko: per-batch offset into B's K dimension (PV slicing of Vt).
template<bool OH>
__global__ void __launch_bounds__(256,1) gemm_h2(
    const __half* __restrict__ A, int lda, long long sA,
    const __half* __restrict__ B, int ldb, long long sB,
    const float* __restrict__ bias, int bias_mode,
    void* __restrict__ C_, int ldc, long long sC,
    int K, int bko)
{
    extern __shared__ __align__(16) unsigned sm[];
    const uint32_t sbase = smem_u32(sm);
    const uint32_t BOFFW = 2*BM*SROWW;   // B region word offset (after 2 A stages)

    const int z  = blockIdx.z;
    const int m0 = blockIdx.y * BM;
    const int n0 = blockIdx.x * BN;
    const int tid  = threadIdx.x;
    const int lane = tid & 31;
    const int wid  = tid >> 5;
    const int grp  = lane >> 2;            // 0..7
    const int qd   = lane & 3;             // 0..3
    const int wm0  = (wid >> 2) * 64;      // warp rows: 2 x 64
    const int wn0  = (wid & 3) * 64;       // warp cols: 4 x 64

    const __half* A0 = A + (size_t)z*sA + (size_t)m0*lda;
    const __half* B0 = B + (size_t)z*sB + (size_t)n0*ldb + (size_t)z*bko;

    float c[4][8][4];
    #pragma unroll
    for (int mi = 0; mi < 4; mi++)
        #pragma unroll
        for (int ni = 0; ni < 8; ni++)
            #pragma unroll
            for (int j = 0; j < 4; j++) c[mi][ni][j] = 0.f;

    const int KT = K / BKH;

    auto issue = [&](int kt, int s){
        #pragma unroll
        for (int i = 0; i < 4; i++){                 // A: 128 rows x 8 chunks / 256 thr
            const int id = tid + 256*i;
            const int row = id >> 3, ch = id & 7;
            cp16(sbase + (s*BM*SROWW + row*SROWW + ch*4)*4,
                 A0 + (size_t)row*lda + kt*BKH + ch*8);
        }
        #pragma unroll
        for (int i = 0; i < 8; i++){                 // B: 256 rows x 8 chunks / 256 thr
            const int id = tid + 256*i;
            const int row = id >> 3, ch = id & 7;
            cp16(sbase + (BOFFW + s*BN*SROWW + row*SROWW + ch*4)*4,
                 B0 + (size_t)row*ldb + kt*BKH + ch*8);
        }
        CP_COMMIT();
    };

    issue(0, 0);
    issue(1, 1);

    for (int kt = 0; kt < KT; kt++){
        if (kt < KT-1) CP_WAIT(1); else CP_WAIT(0);
        __syncthreads();

        const unsigned* As = sm + (kt & 1)*BM*SROWW;
        const unsigned* Bs = sm + BOFFW + (kt & 1)*BN*SROWW;

        #pragma unroll
        for (int ks = 0; ks < NKS; ks++){
            const int kw = ks * 8;
            unsigned af[4][4];
            #pragma unroll
            for (int mi = 0; mi < 4; mi++){
                const int r = wm0 + mi*16 + grp;
                af[mi][0] = As[(r    )*SROWW + kw + qd    ];
                af[mi][1] = As[(r + 8)*SROWW + kw + qd    ];
                af[mi][2] = As[(r    )*SROWW + kw + qd + 4];
                af[mi][3] = As[(r + 8)*SROWW + kw + qd + 4];
            }
            #pragma unroll
            for (int ni = 0; ni < 8; ni++){
                const int col = wn0 + ni*8 + grp;
                const unsigned b0 = Bs[col*SROWW + kw + qd    ];
                const unsigned b1 = Bs[col*SROWW + kw + qd + 4];
                #pragma unroll
                for (int mi = 0; mi < 4; mi++)
                    mma16816(c[mi][ni], af[mi], b0, b1);
            }
        }

        __syncthreads();
        if (kt + 2 < KT) issue(kt + 2, kt & 1);
    }

    // epilogue: c0->(r,cc) c1->(r,cc+1) c2->(r+8,cc) c3->(r+8,cc+1)
    #pragma unroll
    for (int mi = 0; mi < 4; mi++){
        #pragma unroll
        for (int ni = 0; ni < 8; ni++){
            const int r  = m0 + wm0 + mi*16 + grp;
            const int cc = n0 + wn0 + ni*8 + qd*2;
            float v0 = c[mi][ni][0], v1 = c[mi][ni][1];
            float v2 = c[mi][ni][2], v3 = c[mi][ni][3];
            if (bias_mode == 1){
                const float b0 = bias[cc], b1 = bias[cc+1];
                v0 += b0; v1 += b1; v2 += b0; v3 += b1;
            } else if (bias_mode == 2){
                const float b0 = bias[r], b1 = bias[r+8];
                v0 += b0; v1 += b0; v2 += b1; v3 += b1;
            }
            if (OH){
                __half* C = (__half*)C_ + (size_t)z*sC;
                *(__half2*)&C[(size_t)r     * ldc + cc] = __floats2half2_rn(v0, v1);
                *(__half2*)&C[(size_t)(r+8) * ldc + cc] = __floats2half2_rn(v2, v3);
            } else {
                float* C = (float*)C_ + (size_t)z*sC;
                *(float2*)&C[(size_t)r     * ldc + cc] = make_float2(v0, v1);
                *(float2*)&C[(size_t)(r+8) * ldc + cc] = make_float2(v2, v3);
            }
        }
    }
}

// fp32 -> fp16 elementwise (n multiple of 4)
__global__ void __launch_bounds__(256) f2h_k(const float* __restrict__ src,
                                             __half* __restrict__ dst, int n4)
{
    const int i = blockIdx.x * 256 + threadIdx.x;
    if (i < n4){
        float4 v = ((const float4*)src)[i];
        ((__half2*)dst)[2*i  ] = __floats2half2_rn(v.x, v.y);
        ((__half2*)dst)[2*i+1] = __floats2half2_rn(v.z, v.w);
    }
}

// Row softmax over SEQ=4096 fp16 in/out, scale folded in, fp32 math.
__global__ void __launch_bounds__(256) softmax_h(__half* __restrict__ S)
{
    __shared__ float red[8];
    __half* p = S + (size_t)blockIdx.x * SEQ;
    const int tid = threadIdx.x;
    const int lane = tid & 31, wid = tid >> 5;
    const float scale = 0.03125f;   // 1/sqrt(1024)

    uint4 u[2];
    u[0] = ((const uint4*)p)[tid];
    u[1] = ((const uint4*)p)[tid + 256];

    float f[16];
    {
        const unsigned* w = (const unsigned*)u;
        #pragma unroll
        for (int i = 0; i < 8; i++){
            float2 t = h2f2(w[i]);
            f[2*i]   = t.x * scale;
            f[2*i+1] = t.y * scale;
        }
    }

    float mx = -1e30f;
    #pragma unroll
    for (int i = 0; i < 16; i++) mx = fmaxf(mx, f[i]);
    #pragma unroll
    for (int o = 16; o; o >>= 1) mx = fmaxf(mx, __shfl_xor_sync(0xffffffffu, mx, o));
    if (lane == 0) red[wid] = mx;
    __syncthreads();
    mx = red[0];
    #pragma unroll
    for (int w = 1; w < 8; w++) mx = fmaxf(mx, red[w]);
    __syncthreads();

    float sum = 0.f;
    #pragma unroll
    for (int i = 0; i < 16; i++){ f[i] = __expf(f[i] - mx); sum += f[i]; }
    #pragma unroll
    for (int o = 16; o; o >>= 1) sum += __shfl_xor_sync(0xffffffffu, sum, o);
    if (lane == 0) red[wid] = sum;
    __syncthreads();
    sum = red[0];
    #pragma unroll
    for (int w = 1; w < 8; w++) sum += red[w];
    const float inv = 1.0f / sum;

    {
        unsigned* w = (unsigned*)u;
        #pragma unroll
        for (int i = 0; i < 8; i++) w[i] = packh2(f[2*i]*inv, f[2*i+1]*inv);
    }
    ((uint4*)p)[tid]       = u[0];
    ((uint4*)p)[tid + 256] = u[1];
}

extern "C" void kernel_launch(void* const* d_in, const int* in_sizes, int n_in,
                              void* d_out, int out_size)
{
    (void)in_sizes; (void)n_in; (void)out_size;
    const float* X  = (const float*)d_in[0];
    const float* Wq = (const float*)d_in[1];
    const float* bq = (const float*)d_in[2];
    const float* Wk = (const float*)d_in[3];
    const float* bk = (const float*)d_in[4];
    const float* Wv = (const float*)d_in[5];
    const float* bv = (const float*)d_in[6];
    float* out = (float*)d_out;

    __half *xh, *wqh, *wkh, *wvh, *qh, *kh, *vth, *sh;
    cudaGetSymbolAddress((void**)&xh,  g_xh);
    cudaGetSymbolAddress((void**)&wqh, g_wqh);
    cudaGetSymbolAddress((void**)&wkh, g_wkh);
    cudaGetSymbolAddress((void**)&wvh, g_wvh);
    cudaGetSymbolAddress((void**)&qh,  g_qh);
    cudaGetSymbolAddress((void**)&kh,  g_kh);
    cudaGetSymbolAddress((void**)&vth, g_vth);
    cudaGetSymbolAddress((void**)&sh,  g_sh);

    const int SMEM = 2 * (BM + BN) * SROWW * 4;   // 110592 B
    cudaFuncSetAttribute(gemm_h2<true >, cudaFuncAttributeMaxDynamicSharedMemorySize, SMEM);
    cudaFuncSetAttribute(gemm_h2<false>, cudaFuncAttributeMaxDynamicSharedMemorySize, SMEM);

    // convert inputs to fp16
    f2h_k<<<(NROWS*EMB/4 + 255)/256, 256>>>(X,  xh,  NROWS*EMB/4);
    f2h_k<<<(EMB*EMB/4 + 255)/256, 256>>>(Wq, wqh, EMB*EMB/4);
    f2h_k<<<(EMB*EMB/4 + 255)/256, 256>>>(Wk, wkh, EMB*EMB/4);
    f2h_k<<<(EMB*EMB/4 + 255)/256, 256>>>(Wv, wvh, EMB*EMB/4);

    dim3 blk(256, 1, 1);

    // 1) q = X @ Wq^T + bq  -> fp16
    gemm_h2<true><<<dim3(EMB/BN, NROWS/BM, 1), blk, SMEM>>>(
        xh, EMB, 0, wqh, EMB, 0, bq, 1, qh, EMB, 0, EMB, 0);
    // 2) k = X @ Wk^T + bk
    gemm_h2<true><<<dim3(EMB/BN, NROWS/BM, 1), blk, SMEM>>>(
        xh, EMB, 0, wkh, EMB, 0, bk, 1, kh, EMB, 0, EMB, 0);
    // 3) Vt = Wv @ X^T + bv(row) -> fp16 [EMB, NROWS]
    gemm_h2<true><<<dim3(NROWS/BN, EMB/BM, 1), blk, SMEM>>>(
        wvh, EMB, 0, xh, EMB, 0, bv, 2, vth, NROWS, 0, EMB, 0);
    // 4) S[b] = q[b] @ k[b]^T -> fp16 (scale folded into softmax)
    gemm_h2<true><<<dim3(SEQ/BN, SEQ/BM, NB), blk, SMEM>>>(
        qh, EMB, (long long)SEQ*EMB, kh, EMB, (long long)SEQ*EMB, nullptr, 0,
        sh, SEQ, (long long)SEQ*SEQ, EMB, 0);
    // 5) softmax rows
    softmax_h<<<NROWS, 256>>>(sh);
    // 6) out[b] = P[b] @ Vt[:, b*S:(b+1)*S]^T -> fp32
    gemm_h2<false><<<dim3(EMB/BN, SEQ/BM, NB), blk, SMEM>>>(
        sh, SEQ, (long long)SEQ*SEQ, vth, NROWS, 0, nullptr, 0,
        out, EMB, (long long)SEQ*EMB, SEQ, SEQ);
}

// round 6
// speedup vs baseline: 3.0869x; 1.1021x over previous
#include <cuda_runtime.h>
#include <cuda_fp16.h>
#include <cstdint>

#define EMB   1024
#define NB    4
#define SEQ   4096
#define NROWS (NB*SEQ)   // 16384

#define BM    128        // CTA M tile
#define BN    256        // CTA N tile
#define BKH   64         // K halves per stage (4 x k16)
#define SROWW 36         // smem row stride in words; 36%32==4 -> conflict-free frags
#define NKS   4          // k16 steps per stage
#define NSTG  3          // pipeline stages

// fp16 scratch (device globals: allocation-free per harness rules)
__device__ __align__(1024) __half g_xh [(size_t)NROWS*EMB];
__device__ __align__(1024) __half g_wqh[(size_t)EMB*EMB];
__device__ __align__(1024) __half g_wkh[(size_t)EMB*EMB];
__device__ __align__(1024) __half g_wvh[(size_t)EMB*EMB];
__device__ __align__(1024) __half g_qh [(size_t)NB*SEQ*EMB];
__device__ __align__(1024) __half g_kh [(size_t)NB*SEQ*EMB];
__device__ __align__(1024) __half g_vth[(size_t)NB*SEQ*EMB];   // Vt[E, B*S]
__device__ __align__(1024) __half g_sh [(size_t)NB*SEQ*SEQ];   // scores / probs

__device__ __forceinline__ unsigned packh2(float x, float y){
    __half2 h = __floats2half2_rn(x, y);
    return *reinterpret_cast<unsigned*>(&h);
}
__device__ __forceinline__ float2 h2f2(unsigned u){
    __half2 h = *reinterpret_cast<__half2*>(&u);
    return __half22float2(h);
}
__device__ __forceinline__ uint32_t smem_u32(const void* p){
    uint32_t a;
    asm("{ .reg .u64 t; cvta.to.shared.u64 t, %1; cvt.u32.u64 %0, t; }" : "=r"(a) : "l"(p));
    return a;
}
__device__ __forceinline__ void cp16(uint32_t s, const void* g){
    asm volatile("cp.async.ca.shared.global [%0], [%1], 16;" :: "r"(s), "l"(g));
}
#define CP_COMMIT() asm volatile("cp.async.commit_group;" ::: "memory")
#define CP_WAIT(N)  asm volatile("cp.async.wait_group %0;" :: "n"(N) : "memory")

__device__ __forceinline__ void ldsm4(unsigned& r0, unsigned& r1, unsigned& r2, unsigned& r3,
                                      uint32_t addr){
    asm volatile("ldmatrix.sync.aligned.m8n8.x4.shared.b16 {%0,%1,%2,%3}, [%4];"
        : "=r"(r0), "=r"(r1), "=r"(r2), "=r"(r3) : "r"(addr));
}

__device__ __forceinline__ void mma16816(float c[4], const unsigned a[4],
                                         unsigned b0, unsigned b1){
    asm volatile(
        "mma.sync.aligned.m16n8k16.row.col.f32.f16.f16.f32 "
        "{%0,%1,%2,%3},{%4,%5,%6,%7},{%8,%9},{%0,%1,%2,%3};"
        : "+f"(c[0]), "+f"(c[1]), "+f"(c[2]), "+f"(c[3])
        : "r"(a[0]), "r"(a[1]), "r"(a[2]), "r"(a[3]), "r"(b0), "r"(b1));
}

// C[M,N] = A[M,K] * B[N,K]^T (+bias). All-fp16 inputs, K-major, fp32 accum.
// OH: output half (else float). bias_mode: 0 none, 1 col bias[n], 2 row bias[m].
// bko: per-batch offset into B's K dimension (PV slicing of Vt).
template<bool OH>
__global__ void __launch_bounds__(256,1) gemm_h2(
    const __half* __restrict__ A, int lda, long long sA,
    const __half* __restrict__ B, int ldb, long long sB,
    const float* __restrict__ bias, int bias_mode,
    void* __restrict__ C_, int ldc, long long sC,
    int K, int bko)
{
    extern __shared__ __align__(16) unsigned sm[];
    const uint32_t sbase = smem_u32(sm);
    const uint32_t BOFFW = NSTG*BM*SROWW;   // B region word offset (after NSTG A stages)

    const int z  = blockIdx.z;
    const int m0 = blockIdx.y * BM;
    const int n0 = blockIdx.x * BN;
    const int tid  = threadIdx.x;
    const int lane = tid & 31;
    const int wid  = tid >> 5;
    const int qd   = lane & 3;             // 0..3
    const int wm0  = (wid >> 2) * 64;      // warp rows: 2 x 64
    const int wn0  = (wid & 3) * 64;       // warp cols: 4 x 64

    const __half* A0 = A + (size_t)z*sA + (size_t)m0*lda;
    const __half* B0 = B + (size_t)z*sB + (size_t)n0*ldb + (size_t)z*bko;

    // ldmatrix per-lane byte addresses (stage-0 base; add stage/k offsets later)
    // A (x4 per mi): lane -> row (lane&15) within 16-row group, k-half select by lane>>4
    const uint32_t aAddr0 = sbase + (uint32_t)(((wm0 + (lane & 15))*SROWW) * 4) + ((lane >> 4) * 16);
    // B (x4 per ni-pair): lane -> n row (lane&7) + 8*(lane>>4), k-half by (lane>>3)&1
    const uint32_t bAddr0 = sbase + (BOFFW + (uint32_t)(wn0 + ((lane >> 4) * 8) + (lane & 7))*SROWW) * 4
                          + (((lane >> 3) & 1) * 16);

    float c[4][8][4];
    #pragma unroll
    for (int mi = 0; mi < 4; mi++)
        #pragma unroll
        for (int ni = 0; ni < 8; ni++)
            #pragma unroll
            for (int j = 0; j < 4; j++) c[mi][ni][j] = 0.f;

    const int KT = K / BKH;

    auto issue = [&](int kt, int s){
        #pragma unroll
        for (int i = 0; i < 4; i++){                 // A: 128 rows x 8 chunks / 256 thr
            const int id = tid + 256*i;
            const int row = id >> 3, ch = id & 7;
            cp16(sbase + (s*BM*SROWW + row*SROWW + ch*4)*4,
                 A0 + (size_t)row*lda + kt*BKH + ch*8);
        }
        #pragma unroll
        for (int i = 0; i < 8; i++){                 // B: 256 rows x 8 chunks / 256 thr
            const int id = tid + 256*i;
            const int row = id >> 3, ch = id & 7;
            cp16(sbase + (BOFFW + s*BN*SROWW + row*SROWW + ch*4)*4,
                 B0 + (size_t)row*ldb + kt*BKH + ch*8);
        }
        CP_COMMIT();
    };

    issue(0, 0);
    issue(1, 1);

    int stg = 0;                       // kt % NSTG
    int stg2 = 2;                      // (kt+2) % NSTG
    for (int kt = 0; kt < KT; kt++){
        if (kt < KT-1) CP_WAIT(1); else CP_WAIT(0);
        __syncthreads();
        if (kt + 2 < KT) issue(kt + 2, stg2);

        const uint32_t aS = aAddr0 + (uint32_t)stg * (BM*SROWW*4);
        const uint32_t bS = bAddr0 + (uint32_t)stg * (BN*SROWW*4);

        #pragma unroll
        for (int ks = 0; ks < NKS; ks++){
            const uint32_t ko = (uint32_t)(ks * 8 * 4);   // 8 words per k16 step
            unsigned af[4][4];
            #pragma unroll
            for (int mi = 0; mi < 4; mi++)
                ldsm4(af[mi][0], af[mi][1], af[mi][2], af[mi][3],
                      aS + (uint32_t)(mi*16*SROWW*4) + ko);
            #pragma unroll
            for (int np = 0; np < 4; np++){               // ni pair (2*np, 2*np+1)
                unsigned b0, b1, b2, b3;
                ldsm4(b0, b1, b2, b3, bS + (uint32_t)(np*16*SROWW*4) + ko);
                #pragma unroll
                for (int mi = 0; mi < 4; mi++){
                    mma16816(c[mi][2*np  ], af[mi], b0, b1);
                    mma16816(c[mi][2*np+1], af[mi], b2, b3);
                }
            }
        }

        if (++stg  == NSTG) stg  = 0;
        if (++stg2 == NSTG) stg2 = 0;
    }

    // epilogue: c0->(r,cc) c1->(r,cc+1) c2->(r+8,cc) c3->(r+8,cc+1)
    const int grp = lane >> 2;
    #pragma unroll
    for (int mi = 0; mi < 4; mi++){
        #pragma unroll
        for (int ni = 0; ni < 8; ni++){
            const int r  = m0 + wm0 + mi*16 + grp;
            const int cc = n0 + wn0 + ni*8 + qd*2;
            float v0 = c[mi][ni][0], v1 = c[mi][ni][1];
            float v2 = c[mi][ni][2], v3 = c[mi][ni][3];
            if (bias_mode == 1){
                const float b0 = bias[cc], b1 = bias[cc+1];
                v0 += b0; v1 += b1; v2 += b0; v3 += b1;
            } else if (bias_mode == 2){
                const float b0 = bias[r], b1 = bias[r+8];
                v0 += b0; v1 += b0; v2 += b1; v3 += b1;
            }
            if (OH){
                __half* C = (__half*)C_ + (size_t)z*sC;
                *(__half2*)&C[(size_t)r     * ldc + cc] = __floats2half2_rn(v0, v1);
                *(__half2*)&C[(size_t)(r+8) * ldc + cc] = __floats2half2_rn(v2, v3);
            } else {
                float* C = (float*)C_ + (size_t)z*sC;
                *(float2*)&C[(size_t)r     * ldc + cc] = make_float2(v0, v1);
                *(float2*)&C[(size_t)(r+8) * ldc + cc] = make_float2(v2, v3);
            }
        }
    }
}

// fp32 -> fp16 elementwise (n multiple of 4)
__global__ void __launch_bounds__(256) f2h_k(const float* __restrict__ src,
                                             __half* __restrict__ dst, int n4)
{
    const int i = blockIdx.x * 256 + threadIdx.x;
    if (i < n4){
        float4 v = ((const float4*)src)[i];
        ((__half2*)dst)[2*i  ] = __floats2half2_rn(v.x, v.y);
        ((__half2*)dst)[2*i+1] = __floats2half2_rn(v.z, v.w);
    }
}

// Row softmax over SEQ=4096 fp16 in/out, scale folded in, fp32 math (exp2 form).
__global__ void __launch_bounds__(256) softmax_h(__half* __restrict__ S)
{
    __shared__ float red[8];
    __half* p = S + (size_t)blockIdx.x * SEQ;
    const int tid = threadIdx.x;
    const int lane = tid & 31, wid = tid >> 5;
    const float s2 = 0.03125f * 1.4426950408889634f;   // scale * log2(e)

    uint4 u[2];
    u[0] = ((const uint4*)p)[tid];
    u[1] = ((const uint4*)p)[tid + 256];

    float f[16];
    {
        const unsigned* w = (const unsigned*)u;
        #pragma unroll
        for (int i = 0; i < 8; i++){
            float2 t = h2f2(w[i]);
            f[2*i]   = t.x * s2;
            f[2*i+1] = t.y * s2;
        }
    }

    float mx = -1e30f;
    #pragma unroll
    for (int i = 0; i < 16; i++) mx = fmaxf(mx, f[i]);
    #pragma unroll
    for (int o = 16; o; o >>= 1) mx = fmaxf(mx, __shfl_xor_sync(0xffffffffu, mx, o));
    if (lane == 0) red[wid] = mx;
    __syncthreads();
    mx = red[0];
    #pragma unroll
    for (int w = 1; w < 8; w++) mx = fmaxf(mx, red[w]);
    __syncthreads();

    float sum = 0.f;
    #pragma unroll
    for (int i = 0; i < 16; i++){ f[i] = exp2f(f[i] - mx); sum += f[i]; }
    #pragma unroll
    for (int o = 16; o; o >>= 1) sum += __shfl_xor_sync(0xffffffffu, sum, o);
    if (lane == 0) red[wid] = sum;
    __syncthreads();
    sum = red[0];
    #pragma unroll
    for (int w = 1; w < 8; w++) sum += red[w];
    const float inv = 1.0f / sum;

    {
        unsigned* w = (unsigned*)u;
        #pragma unroll
        for (int i = 0; i < 8; i++) w[i] = packh2(f[2*i]*inv, f[2*i+1]*inv);
    }
    ((uint4*)p)[tid]       = u[0];
    ((uint4*)p)[tid + 256] = u[1];
}

extern "C" void kernel_launch(void* const* d_in, const int* in_sizes, int n_in,
                              void* d_out, int out_size)
{
    (void)in_sizes; (void)n_in; (void)out_size;
    const float* X  = (const float*)d_in[0];
    const float* Wq = (const float*)d_in[1];
    const float* bq = (const float*)d_in[2];
    const float* Wk = (const float*)d_in[3];
    const float* bk = (const float*)d_in[4];
    const float* Wv = (const float*)d_in[5];
    const float* bv = (const float*)d_in[6];
    float* out = (float*)d_out;

    __half *xh, *wqh, *wkh, *wvh, *qh, *kh, *vth, *sh;
    cudaGetSymbolAddress((void**)&xh,  g_xh);
    cudaGetSymbolAddress((void**)&wqh, g_wqh);
    cudaGetSymbolAddress((void**)&wkh, g_wkh);
    cudaGetSymbolAddress((void**)&wvh, g_wvh);
    cudaGetSymbolAddress((void**)&qh,  g_qh);
    cudaGetSymbolAddress((void**)&kh,  g_kh);
    cudaGetSymbolAddress((void**)&vth, g_vth);
    cudaGetSymbolAddress((void**)&sh,  g_sh);

    const int SMEM = NSTG * (BM + BN) * SROWW * 4;   // 165888 B
    cudaFuncSetAttribute(gemm_h2<true >, cudaFuncAttributeMaxDynamicSharedMemorySize, SMEM);
    cudaFuncSetAttribute(gemm_h2<false>, cudaFuncAttributeMaxDynamicSharedMemorySize, SMEM);

    // convert inputs to fp16
    f2h_k<<<(NROWS*EMB/4 + 255)/256, 256>>>(X,  xh,  NROWS*EMB/4);
    f2h_k<<<(EMB*EMB/4 + 255)/256, 256>>>(Wq, wqh, EMB*EMB/4);
    f2h_k<<<(EMB*EMB/4 + 255)/256, 256>>>(Wk, wkh, EMB*EMB/4);
    f2h_k<<<(EMB*EMB/4 + 255)/256, 256>>>(Wv, wvh, EMB*EMB/4);

    dim3 blk(256, 1, 1);

    // 1) q = X @ Wq^T + bq  -> fp16
    gemm_h2<true><<<dim3(EMB/BN, NROWS/BM, 1), blk, SMEM>>>(
        xh, EMB, 0, wqh, EMB, 0, bq, 1, qh, EMB, 0, EMB, 0);
    // 2) k = X @ Wk^T + bk
    gemm_h2<true><<<dim3(EMB/BN, NROWS/BM, 1), blk, SMEM>>>(
        xh, EMB, 0, wkh, EMB, 0, bk, 1, kh, EMB, 0, EMB, 0);
    // 3) Vt = Wv @ X^T + bv(row) -> fp16 [EMB, NROWS]
    gemm_h2<true><<<dim3(NROWS/BN, EMB/BM, 1), blk, SMEM>>>(
        wvh, EMB, 0, xh, EMB, 0, bv, 2, vth, NROWS, 0, EMB, 0);
    // 4) S[b] = q[b] @ k[b]^T -> fp16 (scale folded into softmax)
    gemm_h2<true><<<dim3(SEQ/BN, SEQ/BM, NB), blk, SMEM>>>(
        qh, EMB, (long long)SEQ*EMB, kh, EMB, (long long)SEQ*EMB, nullptr, 0,
        sh, SEQ, (long long)SEQ*SEQ, EMB, 0);
    // 5) softmax rows
    softmax_h<<<NROWS, 256>>>(sh);
    // 6) out[b] = P[b] @ Vt[:, b*S:(b+1)*S]^T -> fp32
    gemm_h2<false><<<dim3(EMB/BN, SEQ/BM, NB), blk, SMEM>>>(
        sh, SEQ, (long long)SEQ*SEQ, vth, NROWS, 0, nullptr, 0,
        out, EMB, (long long)SEQ*EMB, SEQ, SEQ);
}